// round 7
// baseline (speedup 1.0000x reference)
#include <cuda_runtime.h>

#define HID 16
#define MAXN 4096
#define WSET 336  // floats per weight set; 336*4=1344B, 16B multiple
#define CHUNKS 8

typedef unsigned long long ull;

__device__ float4 g_pifrac[MAXN];
__device__ float  g_C[9];      // cell / pi
__device__ float  g_invrs;

__device__ __forceinline__ float tanh_ap(float x) {
    float y;
    asm("tanh.approx.f32 %0, %1;" : "=f"(y) : "f"(x));
    return y;
}
__device__ __forceinline__ ull pk2(float a, float b) {
    ull r; asm("mov.b64 %0,{%1,%2};" : "=l"(r) : "f"(a), "f"(b)); return r;
}
__device__ __forceinline__ ull fma2(ull a, ull b, ull c) {
    ull d; asm("fma.rn.f32x2 %0,%1,%2,%3;" : "=l"(d) : "l"(a), "l"(b), "l"(c)); return d;
}
__device__ __forceinline__ void upk2(ull v, float& lo, float& hi) {
    asm("mov.b64 {%0,%1},%2;" : "=f"(lo), "=f"(hi) : "l"(v));
}

__global__ void prep_kernel(const float* __restrict__ x, const float* __restrict__ cell,
                            float* __restrict__ out, int n) {
    __shared__ float sinv[9];
    const float PI = 3.14159265358979323846f;
    if (threadIdx.x == 0) {
        float c[9];
#pragma unroll
        for (int i = 0; i < 9; i++) c[i] = cell[i];
        float det = c[0]*(c[4]*c[8]-c[5]*c[7])
                  - c[1]*(c[3]*c[8]-c[5]*c[6])
                  + c[2]*(c[3]*c[7]-c[4]*c[6]);
        float id = 1.0f / det;
        sinv[0]=(c[4]*c[8]-c[5]*c[7])*id; sinv[1]=(c[2]*c[7]-c[1]*c[8])*id; sinv[2]=(c[1]*c[5]-c[2]*c[4])*id;
        sinv[3]=(c[5]*c[6]-c[3]*c[8])*id; sinv[4]=(c[0]*c[8]-c[2]*c[6])*id; sinv[5]=(c[2]*c[3]-c[0]*c[5])*id;
        sinv[6]=(c[3]*c[7]-c[4]*c[6])*id; sinv[7]=(c[1]*c[6]-c[0]*c[7])*id; sinv[8]=(c[0]*c[4]-c[1]*c[3])*id;
        float volpp = fabsf(det) / (float)n;
        g_invrs = cbrtf(4.0f * PI / (3.0f * volpp));   // 1/rs
#pragma unroll
        for (int i = 0; i < 9; i++) g_C[i] = c[i] / PI;
    }
    __syncthreads();
    for (int i = threadIdx.x; i < n; i += blockDim.x) {
        float x0 = x[3*i+0], x1 = x[3*i+1], x2 = x[3*i+2];
        float f0 = x0*sinv[0] + x1*sinv[3] + x2*sinv[6];
        float f1 = x0*sinv[1] + x1*sinv[4] + x2*sinv[7];
        float f2 = x0*sinv[2] + x1*sinv[5] + x2*sinv[8];
        g_pifrac[i] = make_float4(PI*f0, PI*f1, PI*f2, 0.f);
        out[3*i+0] = x0; out[3*i+1] = x1; out[3*i+2] = x2;
    }
}

// One warp handles (j, 1/CHUNKS slice of i). Each lane processes TWO pairs per
// iteration (i0, i0+32) sharing all weight LDS; layer-2 in packed f32x2 FMAs.
// Straddling chunks are handled by iterating over <=2 uniform segments through
// the same loop body. Register-capped at 128.
__global__ void __launch_bounds__(128, 4) pair_kernel(
    const float* __restrict__ Wp1, const float* __restrict__ bp1,
    const float* __restrict__ Wp2, const float* __restrict__ bp2,
    const float* __restrict__ Wp3, const float* __restrict__ bp3,
    const float* __restrict__ Wa1, const float* __restrict__ ba1,
    const float* __restrict__ Wa2, const float* __restrict__ ba2,
    const float* __restrict__ Wa3, const float* __restrict__ ba3,
    const int* __restrict__ n_up_ptr, float* __restrict__ out, int n)
{
    __shared__ __align__(16) float sw[2 * WSET];
    // layout per set: w1[16] @0, b1[16] @16, w2[256] @32 (row-major [k][h]),
    //                 b2[16] @288, w3[16] @304, b3 @320
    int tid = threadIdx.x;
    if (tid < 16) {
        sw[tid]          = Wp1[tid];
        sw[16 + tid]     = bp1[tid];
        sw[288 + tid]    = bp2[tid];
        sw[304 + tid]    = Wp3[tid];
        sw[WSET + tid]       = Wa1[tid];
        sw[WSET + 16 + tid]  = ba1[tid];
        sw[WSET + 288 + tid] = ba2[tid];
        sw[WSET + 304 + tid] = Wa3[tid];
    }
    if (tid == 16) { sw[320] = bp3[0]; sw[WSET + 320] = ba3[0]; }
    for (int t = tid; t < 256; t += 128) {
        sw[32 + t]        = Wp2[t];
        sw[WSET + 32 + t] = Wa2[t];
    }
    __syncthreads();

    int w    = (blockIdx.x * 128 + tid) >> 5;
    int lane = tid & 31;
    int j    = w >> 3;                 // CHUNKS=8
    if (j >= n) return;
    int csz  = (n + CHUNKS - 1) / CHUNKS;
    int ibeg = (w & (CHUNKS - 1)) * csz;
    int iend = ibeg + csz; if (iend > n) iend = n;
    if (ibeg >= iend) return;

    int  n_up = *n_up_ptr;
    bool j_up = (j < n_up);

    float4 pfj   = g_pifrac[j];
    float  invrs = g_invrs;
    float C00=g_C[0], C01=g_C[1], C02=g_C[2];
    float C10=g_C[3], C11=g_C[4], C12=g_C[5];
    float C20=g_C[6], C21=g_C[7], C22=g_C[8];

    float acc0 = 0.f, acc1 = 0.f, acc2 = 0.f;

    bool straddle = (ibeg < n_up) && (n_up < iend);
    int  nseg     = straddle ? 2 : 1;

    for (int seg = 0; seg < nseg; seg++) {
        int rb = (seg == 0) ? ibeg : n_up;
        int re = (straddle && seg == 0) ? n_up : iend;

        const float*      wb  = sw + (((rb < n_up) == j_up) ? 0 : WSET);
        const float4*     wb4 = (const float4*)wb;
        const ulonglong2* wbp = (const ulonglong2*)wb;

        int i0 = rb + lane;

        // ---- paired loop: lanes cover i0 and i0+32, stride 64 ----
        for (; i0 + 32 < re; i0 += 64) {
            int i1 = i0 + 32;
            float4 pfa = g_pifrac[i0];
            float4 pfb = g_pifrac[i1];
            float a0 = __sinf(pfj.x - pfa.x);
            float a1 = __sinf(pfj.y - pfa.y);
            float a2 = __sinf(pfj.z - pfa.z);
            float c0 = __sinf(pfj.x - pfb.x);
            float c1 = __sinf(pfj.y - pfb.y);
            float c2 = __sinf(pfj.z - pfb.z);
            float vA0 = a0*C00 + a1*C10 + a2*C20;
            float vA1 = a0*C01 + a1*C11 + a2*C21;
            float vA2 = a0*C02 + a1*C12 + a2*C22;
            float vB0 = c0*C00 + c1*C10 + c2*C20;
            float vB1 = c0*C01 + c1*C11 + c2*C21;
            float vB2 = c0*C02 + c1*C12 + c2*C22;
            float sA = sqrtf(vA0*vA0 + vA1*vA1 + vA2*vA2) * invrs;
            float sB = sqrtf(vB0*vB0 + vB1*vB1 + vB2*vB2) * invrs;

            ull gA[8], gB[8];
#pragma unroll
            for (int q = 0; q < 4; q++) {
                ulonglong2 t = wbp[72 + q];
                gA[2*q] = t.x; gA[2*q+1] = t.y;
                gB[2*q] = t.x; gB[2*q+1] = t.y;
            }

#pragma unroll
            for (int k4 = 0; k4 < 4; k4++) {
                float4 w1v = wb4[k4], b1v = wb4[4 + k4];
#pragma unroll
                for (int kk = 0; kk < 4; kk++) {
                    float w1k = kk == 0 ? w1v.x : (kk == 1 ? w1v.y : (kk == 2 ? w1v.z : w1v.w));
                    float b1k = kk == 0 ? b1v.x : (kk == 1 ? b1v.y : (kk == 2 ? b1v.z : b1v.w));
                    int k = 4*k4 + kk;
                    float hA = tanh_ap(fmaf(sA, w1k, b1k));
                    float hB = tanh_ap(fmaf(sB, w1k, b1k));
                    ull hAp = pk2(hA, hA);
                    ull hBp = pk2(hB, hB);
#pragma unroll
                    for (int q = 0; q < 4; q++) {
                        ulonglong2 wv = wbp[8 + 4*k + q];
                        gA[2*q]   = fma2(hAp, wv.x, gA[2*q]);
                        gA[2*q+1] = fma2(hAp, wv.y, gA[2*q+1]);
                        gB[2*q]   = fma2(hBp, wv.x, gB[2*q]);
                        gB[2*q+1] = fma2(hBp, wv.y, gB[2*q+1]);
                    }
                }
            }

            float b3 = wb[320];
            float eaA = b3, ebA = 0.f, eaB = b3, ebB = 0.f;
#pragma unroll
            for (int p = 0; p < 4; p++) {
                float4 w3v = wb4[76 + p];
                float l0, h0, l1, h1;
                upk2(gA[2*p],   l0, h0);
                upk2(gA[2*p+1], l1, h1);
                eaA = fmaf(tanh_ap(l0), w3v.x, eaA);
                ebA = fmaf(tanh_ap(h0), w3v.y, ebA);
                eaA = fmaf(tanh_ap(l1), w3v.z, eaA);
                ebA = fmaf(tanh_ap(h1), w3v.w, ebA);
                upk2(gB[2*p],   l0, h0);
                upk2(gB[2*p+1], l1, h1);
                eaB = fmaf(tanh_ap(l0), w3v.x, eaB);
                ebB = fmaf(tanh_ap(h0), w3v.y, ebB);
                eaB = fmaf(tanh_ap(l1), w3v.z, eaB);
                ebB = fmaf(tanh_ap(h1), w3v.w, ebB);
            }
            float etaA = eaA + ebA; if (i0 == j) etaA = 0.f;
            float etaB = eaB + ebB; if (i1 == j) etaB = 0.f;
            acc0 = fmaf(etaA, vA0, fmaf(etaB, vB0, acc0));
            acc1 = fmaf(etaA, vA1, fmaf(etaB, vB1, acc1));
            acc2 = fmaf(etaA, vA2, fmaf(etaB, vB2, acc2));
        }

        // ---- scalar tail (rare: only when segment length % 64 != 0) ----
        for (; i0 < re; i0 += 32) {
            float4 pfa = g_pifrac[i0];
            float a0 = __sinf(pfj.x - pfa.x);
            float a1 = __sinf(pfj.y - pfa.y);
            float a2 = __sinf(pfj.z - pfa.z);
            float v0 = a0*C00 + a1*C10 + a2*C20;
            float v1 = a0*C01 + a1*C11 + a2*C21;
            float v2 = a0*C02 + a1*C12 + a2*C22;
            float s  = sqrtf(v0*v0 + v1*v1 + v2*v2) * invrs;

            ull g[8];
#pragma unroll
            for (int q = 0; q < 4; q++) {
                ulonglong2 t = wbp[72 + q];
                g[2*q] = t.x; g[2*q+1] = t.y;
            }
#pragma unroll
            for (int k4 = 0; k4 < 4; k4++) {
                float4 w1v = wb4[k4], b1v = wb4[4 + k4];
#pragma unroll
                for (int kk = 0; kk < 4; kk++) {
                    float w1k = kk == 0 ? w1v.x : (kk == 1 ? w1v.y : (kk == 2 ? w1v.z : w1v.w));
                    float b1k = kk == 0 ? b1v.x : (kk == 1 ? b1v.y : (kk == 2 ? b1v.z : b1v.w));
                    int k = 4*k4 + kk;
                    float hk = tanh_ap(fmaf(s, w1k, b1k));
                    ull hp = pk2(hk, hk);
#pragma unroll
                    for (int q = 0; q < 4; q++) {
                        ulonglong2 wv = wbp[8 + 4*k + q];
                        g[2*q]   = fma2(hp, wv.x, g[2*q]);
                        g[2*q+1] = fma2(hp, wv.y, g[2*q+1]);
                    }
                }
            }
            float ea = wb[320], eb = 0.f;
#pragma unroll
            for (int p = 0; p < 4; p++) {
                float4 w3v = wb4[76 + p];
                float l0, h0, l1, h1;
                upk2(g[2*p],   l0, h0);
                upk2(g[2*p+1], l1, h1);
                ea = fmaf(tanh_ap(l0), w3v.x, ea);
                eb = fmaf(tanh_ap(h0), w3v.y, eb);
                ea = fmaf(tanh_ap(l1), w3v.z, ea);
                eb = fmaf(tanh_ap(h1), w3v.w, eb);
            }
            float eta = ea + eb;
            if (i0 == j) eta = 0.f;
            acc0 = fmaf(eta, v0, acc0);
            acc1 = fmaf(eta, v1, acc1);
            acc2 = fmaf(eta, v2, acc2);
        }
    }

#pragma unroll
    for (int o = 16; o > 0; o >>= 1) {
        acc0 += __shfl_xor_sync(0xffffffffu, acc0, o);
        acc1 += __shfl_xor_sync(0xffffffffu, acc1, o);
        acc2 += __shfl_xor_sync(0xffffffffu, acc2, o);
    }
    if (lane == 0) {
        atomicAdd(&out[3*j+0], acc0);
        atomicAdd(&out[3*j+1], acc1);
        atomicAdd(&out[3*j+2], acc2);
    }
}

extern "C" void kernel_launch(void* const* d_in, const int* in_sizes, int n_in,
                              void* d_out, int out_size) {
    const float* x    = (const float*)d_in[0];
    const float* cell = (const float*)d_in[1];
    const float* Wp1  = (const float*)d_in[2];
    const float* bp1  = (const float*)d_in[3];
    const float* Wp2  = (const float*)d_in[4];
    const float* bp2  = (const float*)d_in[5];
    const float* Wp3  = (const float*)d_in[6];
    const float* bp3  = (const float*)d_in[7];
    const float* Wa1  = (const float*)d_in[8];
    const float* ba1  = (const float*)d_in[9];
    const float* Wa2  = (const float*)d_in[10];
    const float* ba2  = (const float*)d_in[11];
    const float* Wa3  = (const float*)d_in[12];
    const float* ba3  = (const float*)d_in[13];
    const int*   n_up = (const int*)d_in[14];
    float* out = (float*)d_out;

    int n = in_sizes[0] / 3;
    prep_kernel<<<1, 256>>>(x, cell, out, n);
    int nwarps = n * CHUNKS;                  // (j, chunk) per warp
    int blocks = (nwarps * 32 + 127) / 128;
    pair_kernel<<<blocks, 128>>>(Wp1, bp1, Wp2, bp2, Wp3, bp3,
                                 Wa1, ba1, Wa2, ba2, Wa3, ba3,
                                 n_up, out, n);
}

// round 8
// speedup vs baseline: 14.0814x; 14.0814x over previous
#include <cuda_runtime.h>

#define HID 16
#define MAXN 4096
#define TAB 8192
#define CHUNKS 8

__device__ float4 g_pifrac[MAXN];
__device__ float  g_C[9];       // cell / pi
__device__ float  g_invrs;
__device__ float  g_sstep;      // table s spacing
__device__ float  g_tscale;     // dist -> table coordinate scale
__device__ float2 g_tab[2][TAB];  // [cls][idx] = (f(s_idx), f(s_idx+1)); cls0=same-spin, cls1=opposite

__global__ void prep_kernel(const float* __restrict__ x, const float* __restrict__ cell,
                            float* __restrict__ out, int n) {
    __shared__ float sinv[9];
    const float PI = 3.14159265358979323846f;
    if (threadIdx.x == 0) {
        float c[9];
#pragma unroll
        for (int i = 0; i < 9; i++) c[i] = cell[i];
        float det = c[0]*(c[4]*c[8]-c[5]*c[7])
                  - c[1]*(c[3]*c[8]-c[5]*c[6])
                  + c[2]*(c[3]*c[7]-c[4]*c[6]);
        float id = 1.0f / det;
        sinv[0]=(c[4]*c[8]-c[5]*c[7])*id; sinv[1]=(c[2]*c[7]-c[1]*c[8])*id; sinv[2]=(c[1]*c[5]-c[2]*c[4])*id;
        sinv[3]=(c[5]*c[6]-c[3]*c[8])*id; sinv[4]=(c[0]*c[8]-c[2]*c[6])*id; sinv[5]=(c[2]*c[3]-c[0]*c[5])*id;
        sinv[6]=(c[3]*c[7]-c[4]*c[6])*id; sinv[7]=(c[1]*c[6]-c[0]*c[7])*id; sinv[8]=(c[0]*c[4]-c[1]*c[3])*id;
        float volpp = fabsf(det) / (float)n;
        float invrs = cbrtf(4.0f * PI / (3.0f * volpp));   // 1/rs
        g_invrs = invrs;
        float r0 = 0.f, r1 = 0.f, r2 = 0.f;
#pragma unroll
        for (int i = 0; i < 9; i++) g_C[i] = c[i] / PI;
        r0 = sqrtf(g_C[0]*g_C[0] + g_C[1]*g_C[1] + g_C[2]*g_C[2]);
        r1 = sqrtf(g_C[3]*g_C[3] + g_C[4]*g_C[4] + g_C[5]*g_C[5]);
        r2 = sqrtf(g_C[6]*g_C[6] + g_C[7]*g_C[7] + g_C[8]*g_C[8]);
        // conservative bound on s = dist*invrs
        float smax = (r0 + r1 + r2) * invrs * 1.0001f;
        g_sstep  = smax / (float)(TAB - 1);
        g_tscale = invrs * (float)(TAB - 1) / smax;   // dist * g_tscale = table coord
    }
    __syncthreads();
    for (int i = threadIdx.x; i < n; i += blockDim.x) {
        float x0 = x[3*i+0], x1 = x[3*i+1], x2 = x[3*i+2];
        float f0 = x0*sinv[0] + x1*sinv[3] + x2*sinv[6];
        float f1 = x0*sinv[1] + x1*sinv[4] + x2*sinv[7];
        float f2 = x0*sinv[2] + x1*sinv[5] + x2*sinv[8];
        g_pifrac[i] = make_float4(PI*f0, PI*f1, PI*f2, 0.f);
        out[3*i+0] = x0; out[3*i+1] = x1; out[3*i+2] = x2;
    }
}

// Build eta lookup tables with ACCURATE tanhf (removes tanh.approx error too).
// 2*TAB threads, one MLP eval each.
__global__ void table_kernel(
    const float* __restrict__ Wp1, const float* __restrict__ bp1,
    const float* __restrict__ Wp2, const float* __restrict__ bp2,
    const float* __restrict__ Wp3, const float* __restrict__ bp3,
    const float* __restrict__ Wa1, const float* __restrict__ ba1,
    const float* __restrict__ Wa2, const float* __restrict__ ba2,
    const float* __restrict__ Wa3, const float* __restrict__ ba3)
{
    int t = blockIdx.x * blockDim.x + threadIdx.x;
    if (t >= 2 * TAB) return;
    int cls = t >> 13;            // TAB = 8192
    int i   = t & (TAB - 1);
    float s = (float)i * g_sstep;

    const float* W1 = cls ? Wa1 : Wp1;
    const float* b1 = cls ? ba1 : bp1;
    const float* W2 = cls ? Wa2 : Wp2;
    const float* b2 = cls ? ba2 : bp2;
    const float* W3 = cls ? Wa3 : Wp3;
    const float* b3 = cls ? ba3 : bp3;

    float h[HID];
#pragma unroll
    for (int k = 0; k < HID; k++) h[k] = tanhf(fmaf(s, W1[k], b1[k]));
    float f = b3[0];
#pragma unroll
    for (int c = 0; c < HID; c++) {
        float g = b2[c];
#pragma unroll
        for (int k = 0; k < HID; k++) g = fmaf(h[k], W2[k*HID + c], g);
        f = fmaf(tanhf(g), W3[c], f);
    }
    g_tab[cls][i].x = f;
    if (i > 0)        g_tab[cls][i-1].y = f;
    if (i == TAB - 1) g_tab[cls][i].y   = f;  // never used (idx<=TAB-2) but keep defined
}

// Pair kernel: grid-stride over (j, chunk) work items; one warp per item.
// Per pair: 3 sin, matvec, sqrt, table lerp, accumulate. No shared memory.
__global__ void __launch_bounds__(256) pair_kernel(
    const int* __restrict__ n_up_ptr, float* __restrict__ out, int n)
{
    int lane   = threadIdx.x & 31;
    int warpId = (blockIdx.x * blockDim.x + threadIdx.x) >> 5;
    int nWarps = (gridDim.x * blockDim.x) >> 5;
    int totalWork = n * CHUNKS;
    int csz = (n + CHUNKS - 1) / CHUNKS;

    int   n_up   = *n_up_ptr;
    float tscale = g_tscale;
    float C00=g_C[0], C01=g_C[1], C02=g_C[2];
    float C10=g_C[3], C11=g_C[4], C12=g_C[5];
    float C20=g_C[6], C21=g_C[7], C22=g_C[8];

    for (int w = warpId; w < totalWork; w += nWarps) {
        int j    = w >> 3;                  // CHUNKS = 8
        int ibeg = (w & (CHUNKS - 1)) * csz;
        int iend = ibeg + csz; if (iend > n) iend = n;
        if (ibeg >= iend) continue;

        bool   j_up = (j < n_up);
        float4 pfj  = g_pifrac[j];
        float acc0 = 0.f, acc1 = 0.f, acc2 = 0.f;

#pragma unroll 2
        for (int i = ibeg + lane; i < iend; i += 32) {
            float4 pfi = g_pifrac[i];
            float s0 = __sinf(pfj.x - pfi.x);
            float s1 = __sinf(pfj.y - pfi.y);
            float s2 = __sinf(pfj.z - pfi.z);
            // v = -d_hsin[i,j]
            float v0 = s0*C00 + s1*C10 + s2*C20;
            float v1 = s0*C01 + s1*C11 + s2*C21;
            float v2 = s0*C02 + s1*C12 + s2*C22;
            float dist = sqrtf(v0*v0 + v1*v1 + v2*v2);

            float t   = dist * tscale;
            int   idx = (int)t;
            idx = idx < (TAB - 2) ? idx : (TAB - 2);
            float fr  = t - (float)idx;
            int   cls = ((i < n_up) == j_up) ? 0 : 1;
            float2 tv = g_tab[cls][idx];
            float eta = fmaf(fr, tv.y - tv.x, tv.x);
            if (i == j) eta = 0.f;

            acc0 = fmaf(eta, v0, acc0);
            acc1 = fmaf(eta, v1, acc1);
            acc2 = fmaf(eta, v2, acc2);
        }

#pragma unroll
        for (int o = 16; o > 0; o >>= 1) {
            acc0 += __shfl_xor_sync(0xffffffffu, acc0, o);
            acc1 += __shfl_xor_sync(0xffffffffu, acc1, o);
            acc2 += __shfl_xor_sync(0xffffffffu, acc2, o);
        }
        if (lane == 0) {
            atomicAdd(&out[3*j+0], acc0);
            atomicAdd(&out[3*j+1], acc1);
            atomicAdd(&out[3*j+2], acc2);
        }
    }
}

extern "C" void kernel_launch(void* const* d_in, const int* in_sizes, int n_in,
                              void* d_out, int out_size) {
    const float* x    = (const float*)d_in[0];
    const float* cell = (const float*)d_in[1];
    const float* Wp1  = (const float*)d_in[2];
    const float* bp1  = (const float*)d_in[3];
    const float* Wp2  = (const float*)d_in[4];
    const float* bp2  = (const float*)d_in[5];
    const float* Wp3  = (const float*)d_in[6];
    const float* bp3  = (const float*)d_in[7];
    const float* Wa1  = (const float*)d_in[8];
    const float* ba1  = (const float*)d_in[9];
    const float* Wa2  = (const float*)d_in[10];
    const float* ba2  = (const float*)d_in[11];
    const float* Wa3  = (const float*)d_in[12];
    const float* ba3  = (const float*)d_in[13];
    const int*   n_up = (const int*)d_in[14];
    float* out = (float*)d_out;

    int n = in_sizes[0] / 3;
    prep_kernel<<<1, 256>>>(x, cell, out, n);
    table_kernel<<<(2 * TAB + 255) / 256, 256>>>(Wp1, bp1, Wp2, bp2, Wp3, bp3,
                                                 Wa1, ba1, Wa2, ba2, Wa3, ba3);
    pair_kernel<<<888, 256>>>(n_up, out, n);   // ~6 blocks/SM, grid-stride balanced
}

// round 10
// speedup vs baseline: 14.3011x; 1.0156x over previous
#include <cuda_runtime.h>

#define HID 16
#define MAXN 4096
#define TAB 8192
#define CHUNKS 8

__device__ float4 g_pifrac[MAXN];
__device__ float  g_C[9];       // cell / pi
__device__ float  g_tscale;     // dist -> table coordinate scale
__device__ float2 g_tab[2][TAB];  // [cls][idx] = (f(s_idx), f(s_idx+1)); cls0=same, cls1=opp

// Merged setup: per-block recompute of cell constants (no cross-block dependency),
// table build with accurate tanhf, pifrac + out copy strided across the grid.
__global__ void __launch_bounds__(256) setup_kernel(
    const float* __restrict__ x, const float* __restrict__ cell,
    const float* __restrict__ Wp1, const float* __restrict__ bp1,
    const float* __restrict__ Wp2, const float* __restrict__ bp2,
    const float* __restrict__ Wp3, const float* __restrict__ bp3,
    const float* __restrict__ Wa1, const float* __restrict__ ba1,
    const float* __restrict__ Wa2, const float* __restrict__ ba2,
    const float* __restrict__ Wa3, const float* __restrict__ ba3,
    float* __restrict__ out, int n)
{
    __shared__ float sh[11];   // sinv[9], sstep, (unused pad)
    const float PI = 3.14159265358979323846f;

    if (threadIdx.x == 0) {
        float c[9];
#pragma unroll
        for (int i = 0; i < 9; i++) c[i] = cell[i];
        float det = c[0]*(c[4]*c[8]-c[5]*c[7])
                  - c[1]*(c[3]*c[8]-c[5]*c[6])
                  + c[2]*(c[3]*c[7]-c[4]*c[6]);
        float id = 1.0f / det;
        sh[0]=(c[4]*c[8]-c[5]*c[7])*id; sh[1]=(c[2]*c[7]-c[1]*c[8])*id; sh[2]=(c[1]*c[5]-c[2]*c[4])*id;
        sh[3]=(c[5]*c[6]-c[3]*c[8])*id; sh[4]=(c[0]*c[8]-c[2]*c[6])*id; sh[5]=(c[2]*c[3]-c[0]*c[5])*id;
        sh[6]=(c[3]*c[7]-c[4]*c[6])*id; sh[7]=(c[1]*c[6]-c[0]*c[7])*id; sh[8]=(c[0]*c[4]-c[1]*c[3])*id;
        float volpp = fabsf(det) / (float)n;
        float invrs = cbrtf(4.0f * PI / (3.0f * volpp));   // 1/rs
        float C0 = c[0]/PI, C1 = c[1]/PI, C2 = c[2]/PI;
        float C3 = c[3]/PI, C4 = c[4]/PI, C5 = c[5]/PI;
        float C6 = c[6]/PI, C7 = c[7]/PI, C8 = c[8]/PI;
        float r0 = sqrtf(C0*C0 + C1*C1 + C2*C2);
        float r1 = sqrtf(C3*C3 + C4*C4 + C5*C5);
        float r2 = sqrtf(C6*C6 + C7*C7 + C8*C8);
        float smax = (r0 + r1 + r2) * invrs * 1.0001f;
        sh[9] = smax / (float)(TAB - 1);                   // sstep
        if (blockIdx.x == 0) {
            g_C[0]=C0; g_C[1]=C1; g_C[2]=C2;
            g_C[3]=C3; g_C[4]=C4; g_C[5]=C5;
            g_C[6]=C6; g_C[7]=C7; g_C[8]=C8;
            g_tscale = invrs * (float)(TAB - 1) / smax;
        }
    }
    __syncthreads();

    int t = blockIdx.x * 256 + threadIdx.x;

    // ---- table entry (threads [0, 2*TAB)) ----
    if (t < 2 * TAB) {
        int cls = t >> 13;            // TAB = 8192
        int i   = t & (TAB - 1);
        float s = (float)i * sh[9];

        const float* W1 = cls ? Wa1 : Wp1;
        const float* b1 = cls ? ba1 : bp1;
        const float* W2 = cls ? Wa2 : Wp2;
        const float* b2 = cls ? ba2 : bp2;
        const float* W3 = cls ? Wa3 : Wp3;
        const float* b3 = cls ? ba3 : bp3;

        float h[HID];
#pragma unroll
        for (int k = 0; k < HID; k++) h[k] = tanhf(fmaf(s, W1[k], b1[k]));
        float f = b3[0];
#pragma unroll
        for (int c = 0; c < HID; c++) {
            float g = b2[c];
#pragma unroll
            for (int k = 0; k < HID; k++) g = fmaf(h[k], W2[k*HID + c], g);
            f = fmaf(tanhf(g), W3[c], f);
        }
        g_tab[cls][i].x = f;
        if (i > 0)        g_tab[cls][i-1].y = f;
        if (i == TAB - 1) g_tab[cls][i].y   = f;
    }

    // ---- pifrac + out copy (grid-strided over n) ----
    int gsz = gridDim.x * 256;
    for (int i = t; i < n; i += gsz) {
        float x0 = x[3*i+0], x1 = x[3*i+1], x2 = x[3*i+2];
        float f0 = x0*sh[0] + x1*sh[3] + x2*sh[6];
        float f1 = x0*sh[1] + x1*sh[4] + x2*sh[7];
        float f2 = x0*sh[2] + x1*sh[5] + x2*sh[8];
        g_pifrac[i] = make_float4(PI*f0, PI*f1, PI*f2, 0.f);
        out[3*i+0] = x0; out[3*i+1] = x1; out[3*i+2] = x2;
    }
}

// Pair kernel: grid-stride over (j, chunk) work items; one warp per item.
__global__ void __launch_bounds__(256) pair_kernel(
    const int* __restrict__ n_up_ptr, float* __restrict__ out, int n)
{
    int lane   = threadIdx.x & 31;
    int warpId = (blockIdx.x * blockDim.x + threadIdx.x) >> 5;
    int nWarps = (gridDim.x * blockDim.x) >> 5;
    int totalWork = n * CHUNKS;
    int csz = (n + CHUNKS - 1) / CHUNKS;

    int   n_up   = *n_up_ptr;
    float tscale = g_tscale;
    float C00=g_C[0], C01=g_C[1], C02=g_C[2];
    float C10=g_C[3], C11=g_C[4], C12=g_C[5];
    float C20=g_C[6], C21=g_C[7], C22=g_C[8];

    for (int w = warpId; w < totalWork; w += nWarps) {
        int j    = w >> 3;                  // CHUNKS = 8
        int ibeg = (w & (CHUNKS - 1)) * csz;
        int iend = ibeg + csz; if (iend > n) iend = n;
        if (ibeg >= iend) continue;

        bool   j_up = (j < n_up);
        float4 pfj  = g_pifrac[j];
        float acc0 = 0.f, acc1 = 0.f, acc2 = 0.f;

#pragma unroll 4
        for (int i = ibeg + lane; i < iend; i += 32) {
            float4 pfi = g_pifrac[i];
            float s0 = __sinf(pfj.x - pfi.x);
            float s1 = __sinf(pfj.y - pfi.y);
            float s2 = __sinf(pfj.z - pfi.z);
            // v = -d_hsin[i,j]
            float v0 = s0*C00 + s1*C10 + s2*C20;
            float v1 = s0*C01 + s1*C11 + s2*C21;
            float v2 = s0*C02 + s1*C12 + s2*C22;
            float dist = sqrtf(v0*v0 + v1*v1 + v2*v2);

            float t   = dist * tscale;
            int   idx = (int)t;
            idx = idx < (TAB - 2) ? idx : (TAB - 2);
            float fr  = t - (float)idx;
            int   cls = ((i < n_up) == j_up) ? 0 : 1;
            float2 tv = g_tab[cls][idx];
            float eta = fmaf(fr, tv.y - tv.x, tv.x);
            if (i == j) eta = 0.f;

            acc0 = fmaf(eta, v0, acc0);
            acc1 = fmaf(eta, v1, acc1);
            acc2 = fmaf(eta, v2, acc2);
        }

#pragma unroll
        for (int o = 16; o > 0; o >>= 1) {
            acc0 += __shfl_xor_sync(0xffffffffu, acc0, o);
            acc1 += __shfl_xor_sync(0xffffffffu, acc1, o);
            acc2 += __shfl_xor_sync(0xffffffffu, acc2, o);
        }
        if (lane == 0) {
            atomicAdd(&out[3*j+0], acc0);
            atomicAdd(&out[3*j+1], acc1);
            atomicAdd(&out[3*j+2], acc2);
        }
    }
}

extern "C" void kernel_launch(void* const* d_in, const int* in_sizes, int n_in,
                              void* d_out, int out_size) {
    const float* x    = (const float*)d_in[0];
    const float* cell = (const float*)d_in[1];
    const float* Wp1  = (const float*)d_in[2];
    const float* bp1  = (const float*)d_in[3];
    const float* Wp2  = (const float*)d_in[4];
    const float* bp2  = (const float*)d_in[5];
    const float* Wp3  = (const float*)d_in[6];
    const float* bp3  = (const float*)d_in[7];
    const float* Wa1  = (const float*)d_in[8];
    const float* ba1  = (const float*)d_in[9];
    const float* Wa2  = (const float*)d_in[10];
    const float* ba2  = (const float*)d_in[11];
    const float* Wa3  = (const float*)d_in[12];
    const float* ba3  = (const float*)d_in[13];
    const int*   n_up = (const int*)d_in[14];
    float* out = (float*)d_out;

    int n = in_sizes[0] / 3;
    setup_kernel<<<(2 * TAB + 255) / 256, 256>>>(x, cell,
                                                 Wp1, bp1, Wp2, bp2, Wp3, bp3,
                                                 Wa1, ba1, Wa2, ba2, Wa3, ba3,
                                                 out, n);
    pair_kernel<<<1536, 256>>>(n_up, out, n);   // 12288 warps = exact work cover
}

// round 11
// speedup vs baseline: 14.4362x; 1.0094x over previous
#include <cuda_runtime.h>

#define HID 16
#define MAXN 4096
#define TAB 4096

__device__ float4 g_pifrac[MAXN];
__device__ float  g_C[9];       // cell / pi
__device__ float  g_tscale;     // dist -> table coordinate scale
__device__ float2 g_tab[2][TAB];  // [cls][idx] = (f(s_idx), f(s_idx+1)); cls0=same, cls1=opp

// Merged setup: per-block recompute of cell constants, table build with accurate
// tanhf, pifrac (padded to 32-multiple) + out copy strided across the grid.
__global__ void __launch_bounds__(256) setup_kernel(
    const float* __restrict__ x, const float* __restrict__ cell,
    const float* __restrict__ Wp1, const float* __restrict__ bp1,
    const float* __restrict__ Wp2, const float* __restrict__ bp2,
    const float* __restrict__ Wp3, const float* __restrict__ bp3,
    const float* __restrict__ Wa1, const float* __restrict__ ba1,
    const float* __restrict__ Wa2, const float* __restrict__ ba2,
    const float* __restrict__ Wa3, const float* __restrict__ ba3,
    float* __restrict__ out, int n)
{
    __shared__ float sh[10];   // sinv[9], sstep
    const float PI = 3.14159265358979323846f;

    if (threadIdx.x == 0) {
        float c[9];
#pragma unroll
        for (int i = 0; i < 9; i++) c[i] = cell[i];
        float det = c[0]*(c[4]*c[8]-c[5]*c[7])
                  - c[1]*(c[3]*c[8]-c[5]*c[6])
                  + c[2]*(c[3]*c[7]-c[4]*c[6]);
        float id = 1.0f / det;
        sh[0]=(c[4]*c[8]-c[5]*c[7])*id; sh[1]=(c[2]*c[7]-c[1]*c[8])*id; sh[2]=(c[1]*c[5]-c[2]*c[4])*id;
        sh[3]=(c[5]*c[6]-c[3]*c[8])*id; sh[4]=(c[0]*c[8]-c[2]*c[6])*id; sh[5]=(c[2]*c[3]-c[0]*c[5])*id;
        sh[6]=(c[3]*c[7]-c[4]*c[6])*id; sh[7]=(c[1]*c[6]-c[0]*c[7])*id; sh[8]=(c[0]*c[4]-c[1]*c[3])*id;
        float volpp = fabsf(det) / (float)n;
        float invrs = cbrtf(4.0f * PI / (3.0f * volpp));   // 1/rs
        float C0 = c[0]/PI, C1 = c[1]/PI, C2 = c[2]/PI;
        float C3 = c[3]/PI, C4 = c[4]/PI, C5 = c[5]/PI;
        float C6 = c[6]/PI, C7 = c[7]/PI, C8 = c[8]/PI;
        float r0 = sqrtf(C0*C0 + C1*C1 + C2*C2);
        float r1 = sqrtf(C3*C3 + C4*C4 + C5*C5);
        float r2 = sqrtf(C6*C6 + C7*C7 + C8*C8);
        float smax = (r0 + r1 + r2) * invrs * 1.0001f;
        sh[9] = smax / (float)(TAB - 1);                   // sstep
        if (blockIdx.x == 0) {
            g_C[0]=C0; g_C[1]=C1; g_C[2]=C2;
            g_C[3]=C3; g_C[4]=C4; g_C[5]=C5;
            g_C[6]=C6; g_C[7]=C7; g_C[8]=C8;
            g_tscale = invrs * (float)(TAB - 1) / smax;
        }
    }
    __syncthreads();

    int t = blockIdx.x * 256 + threadIdx.x;

    // ---- table entry (threads [0, 2*TAB)) ----
    if (t < 2 * TAB) {
        int cls = t / TAB;
        int i   = t % TAB;
        float s = (float)i * sh[9];

        const float* W1 = cls ? Wa1 : Wp1;
        const float* b1 = cls ? ba1 : bp1;
        const float* W2 = cls ? Wa2 : Wp2;
        const float* b2 = cls ? ba2 : bp2;
        const float* W3 = cls ? Wa3 : Wp3;
        const float* b3 = cls ? ba3 : bp3;

        float h[HID];
#pragma unroll
        for (int k = 0; k < HID; k++) h[k] = tanhf(fmaf(s, W1[k], b1[k]));
        float f = b3[0];
#pragma unroll
        for (int c = 0; c < HID; c++) {
            float g = b2[c];
#pragma unroll
            for (int k = 0; k < HID; k++) g = fmaf(h[k], W2[k*HID + c], g);
            f = fmaf(tanhf(g), W3[c], f);
        }
        g_tab[cls][i].x = f;
        if (i > 0)        g_tab[cls][i-1].y = f;
        if (i == TAB - 1) g_tab[cls][i].y   = f;
    }

    // ---- pifrac (padded to 32 multiple) + out copy ----
    int npad = (n + 31) & ~31;
    int gsz  = gridDim.x * 256;
    for (int i = t; i < npad; i += gsz) {
        if (i < n) {
            float x0 = x[3*i+0], x1 = x[3*i+1], x2 = x[3*i+2];
            float f0 = x0*sh[0] + x1*sh[3] + x2*sh[6];
            float f1 = x0*sh[1] + x1*sh[4] + x2*sh[7];
            float f2 = x0*sh[2] + x1*sh[5] + x2*sh[8];
            g_pifrac[i] = make_float4(PI*f0, PI*f1, PI*f2, 0.f);
            out[3*i+0] = x0; out[3*i+1] = x1; out[3*i+2] = x2;
        } else {
            g_pifrac[i] = make_float4(0.f, 0.f, 0.f, 0.f);
        }
    }
}

// Symmetric systolic pair kernel: one warp per 32x32 block-tile (bi <= bj).
// Lane owns column i (fixed); row features + row accumulator rotate by shuffle.
// Each evaluated pair contributes to dr[j] (rotating acc) and dr[i] (mirror,
// sign-flipped). Diagonal tiles: row side only, i==j zeroed.
__global__ void __launch_bounds__(128) pair_kernel(
    const int* __restrict__ n_up_ptr, float* __restrict__ out, int n)
{
    int lane   = threadIdx.x & 31;
    int warpId = (blockIdx.x * blockDim.x + threadIdx.x) >> 5;
    int nWarps = (gridDim.x * blockDim.x) >> 5;
    int nb = (n + 31) >> 5;
    int nt = nb * (nb + 1) / 2;

    int   n_up   = *n_up_ptr;
    float tscale = g_tscale;
    float C00=g_C[0], C01=g_C[1], C02=g_C[2];
    float C10=g_C[3], C11=g_C[4], C12=g_C[5];
    float C20=g_C[6], C21=g_C[7], C22=g_C[8];

    for (int t = warpId; t < nt; t += nWarps) {
        // invert triangular index: t = bj*(bj+1)/2 + bi, 0 <= bi <= bj
        int bj = (int)((sqrtf(8.0f * (float)t + 1.0f) - 1.0f) * 0.5f);
        while ((bj + 1) * (bj + 2) / 2 <= t) bj++;
        while (bj * (bj + 1) / 2 > t) bj--;
        int bi = t - bj * (bj + 1) / 2;
        int Ib = bi << 5, Jb = bj << 5;
        bool diag = (bi == bj);

        int    i    = Ib + lane;
        float4 pfi  = g_pifrac[i];
        bool   i_up = (i < n_up);
        bool   i_ok = (i < n);

        float4 pfj = g_pifrac[Jb + lane];   // row slot: starts as row Jb+lane
        float ra0=0.f, ra1=0.f, ra2=0.f;    // acc for the row currently held
        float ca0=0.f, ca1=0.f, ca2=0.f;    // acc for column i (lane-fixed)

#pragma unroll 4
        for (int k = 0; k < 32; k++) {
            int jrow = Jb + ((lane + k) & 31);   // row this lane holds at step k

            float s0 = __sinf(pfj.x - pfi.x);
            float s1 = __sinf(pfj.y - pfi.y);
            float s2 = __sinf(pfj.z - pfi.z);
            // v: dr[jrow] direction (j-centric)
            float v0 = s0*C00 + s1*C10 + s2*C20;
            float v1 = s0*C01 + s1*C11 + s2*C21;
            float v2 = s0*C02 + s1*C12 + s2*C22;
            float q  = v0*v0 + v1*v1 + v2*v2;
            float dist;
            asm("sqrt.approx.f32 %0, %1;" : "=f"(dist) : "f"(q));

            float tt  = dist * tscale;
            int   idx = (int)tt;
            idx = idx < (TAB - 2) ? idx : (TAB - 2);
            float fr  = tt - (float)idx;
            int   cls = ((jrow < n_up) == i_up) ? 0 : 1;
            float2 tv = g_tab[cls][idx];
            float eta = fmaf(fr, tv.y - tv.x, tv.x);

            bool valid = i_ok && (jrow < n) && !(diag && (jrow == i));
            eta = valid ? eta : 0.f;

            ra0 = fmaf(eta, v0, ra0);
            ra1 = fmaf(eta, v1, ra1);
            ra2 = fmaf(eta, v2, ra2);
            ca0 = fmaf(-eta, v0, ca0);
            ca1 = fmaf(-eta, v1, ca1);
            ca2 = fmaf(-eta, v2, ca2);

            // rotate row data + row acc: lane l receives lane l+1's values
            pfj.x = __shfl_sync(0xffffffffu, pfj.x, lane + 1);
            pfj.y = __shfl_sync(0xffffffffu, pfj.y, lane + 1);
            pfj.z = __shfl_sync(0xffffffffu, pfj.z, lane + 1);
            ra0   = __shfl_sync(0xffffffffu, ra0,   lane + 1);
            ra1   = __shfl_sync(0xffffffffu, ra1,   lane + 1);
            ra2   = __shfl_sync(0xffffffffu, ra2,   lane + 1);
        }

        // after 32 rotations, lane l holds the accumulator for row Jb+l
        int jr = Jb + lane;
        if (jr < n) {
            atomicAdd(&out[3*jr+0], ra0);
            atomicAdd(&out[3*jr+1], ra1);
            atomicAdd(&out[3*jr+2], ra2);
        }
        if (!diag && i_ok) {
            atomicAdd(&out[3*i+0], ca0);
            atomicAdd(&out[3*i+1], ca1);
            atomicAdd(&out[3*i+2], ca2);
        }
    }
}

extern "C" void kernel_launch(void* const* d_in, const int* in_sizes, int n_in,
                              void* d_out, int out_size) {
    const float* x    = (const float*)d_in[0];
    const float* cell = (const float*)d_in[1];
    const float* Wp1  = (const float*)d_in[2];
    const float* bp1  = (const float*)d_in[3];
    const float* Wp2  = (const float*)d_in[4];
    const float* bp2  = (const float*)d_in[5];
    const float* Wp3  = (const float*)d_in[6];
    const float* bp3  = (const float*)d_in[7];
    const float* Wa1  = (const float*)d_in[8];
    const float* ba1  = (const float*)d_in[9];
    const float* Wa2  = (const float*)d_in[10];
    const float* ba2  = (const float*)d_in[11];
    const float* Wa3  = (const float*)d_in[12];
    const float* ba3  = (const float*)d_in[13];
    const int*   n_up = (const int*)d_in[14];
    float* out = (float*)d_out;

    int n = in_sizes[0] / 3;
    setup_kernel<<<(2 * TAB + 255) / 256, 256>>>(x, cell,
                                                 Wp1, bp1, Wp2, bp2, Wp3, bp3,
                                                 Wa1, ba1, Wa2, ba2, Wa3, ba3,
                                                 out, n);
    int nb = (n + 31) / 32;
    int nt = nb * (nb + 1) / 2;
    int blocks = (nt * 32 + 127) / 128;
    pair_kernel<<<blocks, 128>>>(n_up, out, n);
}